// round 13
// baseline (speedup 1.0000x reference)
#include <cuda_runtime.h>
#include <cuda_bf16.h>
#include <math.h>
#include <stdint.h>

#define B_   8
#define SQ_  2048
#define SKV_ 2048
#define D_   1024

typedef __nv_bfloat16 bf16;

// ---------------------------------------------------------------------------
// Device scratch (allocation-free per harness rules)
// ---------------------------------------------------------------------------
__device__ bf16 g_tH [16777216], g_tL [16777216];   // target split
__device__ bf16 g_nH [16777216], g_nL [16777216];   // non_target split
__device__ bf16 g_WqH[ 1048576], g_WqL[ 1048576];
__device__ bf16 g_WkH[ 1048576], g_WkL[ 1048576];
__device__ bf16 g_WvH[ 1048576], g_WvL[ 1048576];
__device__ bf16 g_QH [16777216], g_QL [16777216];
__device__ bf16 g_KH [16777216], g_KL [16777216];
__device__ bf16 g_VtH[16777216], g_VtL[16777216];   // V^T per batch [b][d][kv]
__device__ float g_S [33554432];                    // scores fp32
__device__ bf16 g_PH [33554432], g_PL [33554432];   // probs split

__device__ __forceinline__ uint32_t smem_u32(const void* p) {
    uint32_t a;
    asm("{ .reg .u64 t; cvta.to.shared.u64 t, %1; cvt.u32.u64 %0, t; }" : "=r"(a) : "l"(p));
    return a;
}

// ---------------------------------------------------------------------------
// Warp-MMA primitives (sm_80 baseline; safe under compute_103)
// ---------------------------------------------------------------------------
#define LDSM4(r, ad) \
    asm volatile("ldmatrix.sync.aligned.m8n8.x4.shared.b16 {%0,%1,%2,%3}, [%4];" \
        : "=r"((r)[0]), "=r"((r)[1]), "=r"((r)[2]), "=r"((r)[3]) : "r"(ad))

#define MMA_BF16(c, a, b) \
    asm volatile("mma.sync.aligned.m16n8k16.row.col.f32.bf16.bf16.f32 " \
        "{%0,%1,%2,%3}, {%4,%5,%6,%7}, {%8,%9}, {%0,%1,%2,%3};" \
        : "+f"((c)[0]), "+f"((c)[1]), "+f"((c)[2]), "+f"((c)[3]) \
        : "r"((a)[0]), "r"((a)[1]), "r"((a)[2]), "r"((a)[3]), \
          "r"((b)[0]), "r"((b)[1]))

#define CP_ASYNC16(dst, src) \
    asm volatile("cp.async.cg.shared.global [%0], [%1], 16;" :: "r"(dst), "l"(src))
#define CP_COMMIT()  asm volatile("cp.async.commit_group;" ::: "memory")
#define CP_WAIT1()   asm volatile("cp.async.wait_group 1;" ::: "memory")

// ---------------------------------------------------------------------------
// Split-bf16 NT GEMM: C = (Ah+Al)(Bh+Bl)^T ~= hh+lh+hl (+bias)
// CTA tile 256x128, BK=32, 16 warps (4m x 4n, warp tile 64x32), 512 threads.
// Phased products keep live fragment registers <= ~40 so the 128-reg cap of
// 512 threads is met WITHOUT spills. 4 warps/SMSP cover load-phase latency.
// EPI: 0 = fp32 C, 1 = split-bf16 + bias, 2 = split-bf16 transposed + bias
// ---------------------------------------------------------------------------
#define STAGES 3
#define ROWB   80                          // 32 bf16 (64B) + 16B pad
#define APLANE (256 * ROWB)                // 20480 B
#define BPLANE (128 * ROWB)                // 10240 B
#define OFF_AH 0
#define OFF_AL APLANE
#define OFF_BH (2 * APLANE)
#define OFF_BL (2 * APLANE + BPLANE)
#define STAGE_BYTES (2 * APLANE + 2 * BPLANE)   // 61440 B
#define SMEM_BYTES (STAGES * STAGE_BYTES)       // 184320 B

template <int EPI>
__global__ void __launch_bounds__(512, 1)
mma_nt(const bf16* __restrict__ Ah, const bf16* __restrict__ Al,
       const bf16* __restrict__ Bh, const bf16* __restrict__ Bl,
       void* __restrict__ C0, void* __restrict__ C1,
       const float* __restrict__ bias,
       int K, int ldC,
       long long sA, long long sB, long long sC, int batchRows)
{
    extern __shared__ __align__(128) char smem[];
    const uint32_t sbase = smem_u32(smem);
    const int tid  = threadIdx.x;
    const int lane = tid & 31;
    const int wid  = tid >> 5;
    const int wm   = wid & 3;      // 4 warps along m (64 rows each)
    const int wn   = wid >> 2;     // 4 warps along n (32 cols each)

    Ah += (long long)blockIdx.z * sA;  Al += (long long)blockIdx.z * sA;
    Bh += (long long)blockIdx.z * sB;  Bl += (long long)blockIdx.z * sB;

    const int m0 = blockIdx.y * 256;
    const int n0 = blockIdx.x * 128;
    const int nChunks = K >> 5;

    // --- cp.async one K-chunk into a stage: A 2x256x64B + B 2x128x64B ------
    // 3072 16B-chunks over 512 threads = 6 per thread.
    auto issue = [&](int t) {
        if (t < nChunks) {
            const int stage = t % STAGES;
            const uint32_t sb = sbase + stage * STAGE_BYTES;
            const int k0 = t << 5;
#pragma unroll
            for (int i = 0; i < 6; ++i) {
                const int idx = tid + (i << 9);       // 0..3071
                if (idx < 2048) {                     // A planes
                    const int c = idx & 3;
                    const int r = (idx >> 2) & 255;
                    const int p = idx >> 10;          // 0 = hi, 1 = lo
                    const bf16* src = (p ? Al : Ah) + (size_t)(m0 + r) * K + k0 + c * 8;
                    const uint32_t dst = sb + (p ? OFF_AL : OFF_AH) + r * ROWB + c * 16;
                    CP_ASYNC16(dst, src);
                } else {                              // B planes
                    const int j = idx - 2048;
                    const int c = j & 3;
                    const int r = (j >> 2) & 127;
                    const int p = j >> 9;
                    const bf16* src = (p ? Bl : Bh) + (size_t)(n0 + r) * K + k0 + c * 8;
                    const uint32_t dst = sb + (p ? OFF_BL : OFF_BH) + r * ROWB + c * 16;
                    CP_ASYNC16(dst, src);
                }
            }
        }
        CP_COMMIT();
    };

    float acc[4][4][4];
#pragma unroll
    for (int mi = 0; mi < 4; ++mi)
#pragma unroll
        for (int ni = 0; ni < 4; ++ni)
#pragma unroll
            for (int e = 0; e < 4; ++e) acc[mi][ni][e] = 0.0f;

    const uint32_t arow = (uint32_t)(wm * 64 + (lane & 15));
    const uint32_t abit = (uint32_t)((lane >> 4) << 4);
    const uint32_t brow = (uint32_t)(wn * 32 + (lane & 7) + ((lane >> 4) << 3));
    const uint32_t bbit = (uint32_t)(((lane >> 3) & 1) << 4);

    issue(0);
    issue(1);

    for (int t = 0; t < nChunks; ++t) {
        CP_WAIT1();          // chunk t resident (this thread); t+1 in flight
        __syncthreads();     // chunk t visible to all warps; stage (t+2)%3 free
        issue(t + 2);

        const uint32_t st = sbase + (t % STAGES) * STAGE_BYTES;
#pragma unroll
        for (int ks = 0; ks < 2; ++ks) {
            uint32_t fAh[4][4], fAl[4][4], fBh[2][4], fBl[2][4];
            const uint32_t akoff = (uint32_t)(ks << 5) + abit;
            const uint32_t bkoff = (uint32_t)(ks << 5) + bbit;

            // phase 1: hi x hi
#pragma unroll
            for (int mi = 0; mi < 4; ++mi)
                LDSM4(fAh[mi], st + OFF_AH + (arow + mi * 16) * ROWB + akoff);
#pragma unroll
            for (int np = 0; np < 2; ++np)
                LDSM4(fBh[np], st + OFF_BH + (brow + np * 16) * ROWB + bkoff);
#pragma unroll
            for (int mi = 0; mi < 4; ++mi)
#pragma unroll
                for (int ni = 0; ni < 4; ++ni)
                    MMA_BF16(acc[mi][ni], fAh[mi], (&fBh[ni >> 1][(ni & 1) << 1]));

            // phase 2: lo x hi (Bh still live, Al loaded now)
#pragma unroll
            for (int mi = 0; mi < 4; ++mi)
                LDSM4(fAl[mi], st + OFF_AL + (arow + mi * 16) * ROWB + akoff);
#pragma unroll
            for (int mi = 0; mi < 4; ++mi)
#pragma unroll
                for (int ni = 0; ni < 4; ++ni)
                    MMA_BF16(acc[mi][ni], fAl[mi], (&fBh[ni >> 1][(ni & 1) << 1]));

            // phase 3: hi x lo (Ah still live, Bl loaded now; Al/Bh dead)
#pragma unroll
            for (int np = 0; np < 2; ++np)
                LDSM4(fBl[np], st + OFF_BL + (brow + np * 16) * ROWB + bkoff);
#pragma unroll
            for (int mi = 0; mi < 4; ++mi)
#pragma unroll
                for (int ni = 0; ni < 4; ++ni)
                    MMA_BF16(acc[mi][ni], fAh[mi], (&fBl[ni >> 1][(ni & 1) << 1]));
        }
    }

    // ---------------------------- epilogue ---------------------------------
    const int qr = lane >> 2;          // 0..7
    const int qc = (lane & 3) << 1;    // 0,2,4,6

#pragma unroll
    for (int mi = 0; mi < 4; ++mi) {
        const int gm0 = m0 + wm * 64 + mi * 16 + qr;   // row, and gm0+8
#pragma unroll
        for (int ni = 0; ni < 4; ++ni) {
            const int gn = n0 + wn * 32 + ni * 8 + qc;
            float v00 = acc[mi][ni][0], v01 = acc[mi][ni][1];
            float v10 = acc[mi][ni][2], v11 = acc[mi][ni][3];

            if (EPI == 0) {
                float* C = (float*)C0 + (long long)blockIdx.z * sC;
                *reinterpret_cast<float2*>(C + (size_t)gm0 * ldC + gn)
                    = make_float2(v00, v01);
                *reinterpret_cast<float2*>(C + (size_t)(gm0 + 8) * ldC + gn)
                    = make_float2(v10, v11);
            } else {
                const float b0v = bias[gn], b1v = bias[gn + 1];
                v00 += b0v; v01 += b1v; v10 += b0v; v11 += b1v;
                bf16 h00 = __float2bfloat16(v00);
                bf16 h01 = __float2bfloat16(v01);
                bf16 h10 = __float2bfloat16(v10);
                bf16 h11 = __float2bfloat16(v11);
                bf16 l00 = __float2bfloat16(v00 - __bfloat162float(h00));
                bf16 l01 = __float2bfloat16(v01 - __bfloat162float(h01));
                bf16 l10 = __float2bfloat16(v10 - __bfloat162float(h10));
                bf16 l11 = __float2bfloat16(v11 - __bfloat162float(h11));
                bf16* CH = (bf16*)C0;
                bf16* CL = (bf16*)C1;
                if (EPI == 1) {
                    __nv_bfloat162 hp0; hp0.x = h00; hp0.y = h01;
                    __nv_bfloat162 hp1; hp1.x = h10; hp1.y = h11;
                    __nv_bfloat162 lp0; lp0.x = l00; lp0.y = l01;
                    __nv_bfloat162 lp1; lp1.x = l10; lp1.y = l11;
                    *reinterpret_cast<__nv_bfloat162*>(CH + (size_t)gm0 * ldC + gn) = hp0;
                    *reinterpret_cast<__nv_bfloat162*>(CH + (size_t)(gm0 + 8) * ldC + gn) = hp1;
                    *reinterpret_cast<__nv_bfloat162*>(CL + (size_t)gm0 * ldC + gn) = lp0;
                    *reinterpret_cast<__nv_bfloat162*>(CL + (size_t)(gm0 + 8) * ldC + gn) = lp1;
                } else {  // EPI == 2: V^T scatter (gm -> (bb, s), col-major per batch)
                    const int bb = gm0 / batchRows;
                    const int s0 = gm0 - bb * batchRows;
                    const size_t colbase = ((size_t)bb * ldC + gn) * (size_t)batchRows;
                    CH[colbase + s0]                  = h00;
                    CH[colbase + batchRows + s0]      = h01;
                    CH[colbase + s0 + 8]              = h10;
                    CH[colbase + batchRows + s0 + 8]  = h11;
                    CL[colbase + s0]                  = l00;
                    CL[colbase + batchRows + s0]      = l01;
                    CL[colbase + s0 + 8]              = l10;
                    CL[colbase + batchRows + s0 + 8]  = l11;
                }
            }
        }
    }
}

// ---------------------------------------------------------------------------
// Split helpers: fp32 -> (bf16 hi, bf16 lo), 8 elems/thread, fully coalesced.
// ---------------------------------------------------------------------------
__device__ __forceinline__ void split8(const float* __restrict__ x,
                                       bf16* __restrict__ h, bf16* __restrict__ l,
                                       int i)
{
    const float4 a = reinterpret_cast<const float4*>(x)[2 * i];
    const float4 b = reinterpret_cast<const float4*>(x)[2 * i + 1];
    float v[8] = { a.x, a.y, a.z, a.w, b.x, b.y, b.z, b.w };
    __align__(16) bf16 hb[8];
    __align__(16) bf16 lb[8];
#pragma unroll
    for (int j = 0; j < 8; ++j) {
        bf16 hh = __float2bfloat16(v[j]);
        hb[j] = hh;
        lb[j] = __float2bfloat16(v[j] - __bfloat162float(hh));
    }
    reinterpret_cast<uint4*>(h)[i] = *reinterpret_cast<uint4*>(hb);
    reinterpret_cast<uint4*>(l)[i] = *reinterpret_cast<uint4*>(lb);
}

// target + non_target in ONE launch
__global__ void split_two(const float* __restrict__ x0, bf16* __restrict__ h0, bf16* __restrict__ l0,
                          const float* __restrict__ x1, bf16* __restrict__ h1, bf16* __restrict__ l1)
{
    int b = blockIdx.x;
    const float* x; bf16 *h, *l;
    if (b < 8192) { x = x0; h = h0; l = l0; }
    else          { x = x1; h = h1; l = l1; b -= 8192; }
    split8(x, h, l, b * 256 + (int)threadIdx.x);
}

// three weight matrices in ONE launch: 512 blocks each
__global__ void split_w3(const float* __restrict__ wq, bf16* __restrict__ qh, bf16* __restrict__ ql,
                         const float* __restrict__ wk, bf16* __restrict__ kh, bf16* __restrict__ kl,
                         const float* __restrict__ wv, bf16* __restrict__ vh, bf16* __restrict__ vl)
{
    int b = blockIdx.x;
    const float* x; bf16 *h, *l;
    if (b < 512)       { x = wq; h = qh; l = ql; }
    else if (b < 1024) { x = wk; h = kh; l = kl; b -= 512; }
    else               { x = wv; h = vh; l = vl; b -= 1024; }
    split8(x, h, l, b * 256 + (int)threadIdx.x);
}

// ---------------------------------------------------------------------------
// Row softmax (2048 cols) fused with split-bf16 conversion; vectorized
// ---------------------------------------------------------------------------
__global__ __launch_bounds__(256)
void softmax_split(const float* __restrict__ S, bf16* __restrict__ Ph, bf16* __restrict__ Pl)
{
    const size_t base = (size_t)blockIdx.x * SKV_;
    const float* p = S + base;
    const int tid = threadIdx.x;
    const int lane = tid & 31;
    const int warp = tid >> 5;
    __shared__ float red[8];

    const float4 a = reinterpret_cast<const float4*>(p)[2 * tid];
    const float4 b = reinterpret_cast<const float4*>(p)[2 * tid + 1];
    float v[8] = { a.x, a.y, a.z, a.w, b.x, b.y, b.z, b.w };

    float m = -INFINITY;
#pragma unroll
    for (int i = 0; i < 8; ++i) m = fmaxf(m, v[i]);
#pragma unroll
    for (int o = 16; o > 0; o >>= 1) m = fmaxf(m, __shfl_xor_sync(0xffffffffu, m, o));
    if (lane == 0) red[warp] = m;
    __syncthreads();
    float mrow = red[0];
#pragma unroll
    for (int w = 1; w < 8; ++w) mrow = fmaxf(mrow, red[w]);
    __syncthreads();

    float s = 0.0f;
#pragma unroll
    for (int i = 0; i < 8; ++i) { v[i] = expf(v[i] - mrow); s += v[i]; }
#pragma unroll
    for (int o = 16; o > 0; o >>= 1) s += __shfl_xor_sync(0xffffffffu, s, o);
    if (lane == 0) red[warp] = s;
    __syncthreads();
    float srow = 0.0f;
#pragma unroll
    for (int w = 0; w < 8; ++w) srow += red[w];
    const float inv = 1.0f / srow;

    __align__(16) bf16 hb[8];
    __align__(16) bf16 lb[8];
#pragma unroll
    for (int i = 0; i < 8; ++i) {
        float pv = v[i] * inv;
        bf16 h = __float2bfloat16(pv);
        hb[i] = h;
        lb[i] = __float2bfloat16(pv - __bfloat162float(h));
    }
    reinterpret_cast<uint4*>(Ph + base)[tid] = *reinterpret_cast<uint4*>(hb);
    reinterpret_cast<uint4*>(Pl + base)[tid] = *reinterpret_cast<uint4*>(lb);
}

// ---------------------------------------------------------------------------
// Launch
// ---------------------------------------------------------------------------
extern "C" void kernel_launch(void* const* d_in, const int* in_sizes, int n_in,
                              void* d_out, int out_size)
{
    const float* target     = (const float*)d_in[0];
    const float* non_target = (const float*)d_in[1];
    const float* Wq = (const float*)d_in[2];
    const float* bq = (const float*)d_in[3];
    const float* Wk = (const float*)d_in[4];
    const float* bk = (const float*)d_in[5];
    const float* Wv = (const float*)d_in[6];
    const float* bv = (const float*)d_in[7];
    float* out = (float*)d_out;

    bf16 *tH, *tL, *nH, *nL, *WqH, *WqL, *WkH, *WkL, *WvH, *WvL;
    bf16 *QH, *QL, *KH, *KL, *VtH, *VtL, *PH, *PL;
    float* S;
    cudaGetSymbolAddress((void**)&tH,  g_tH);  cudaGetSymbolAddress((void**)&tL,  g_tL);
    cudaGetSymbolAddress((void**)&nH,  g_nH);  cudaGetSymbolAddress((void**)&nL,  g_nL);
    cudaGetSymbolAddress((void**)&WqH, g_WqH); cudaGetSymbolAddress((void**)&WqL, g_WqL);
    cudaGetSymbolAddress((void**)&WkH, g_WkH); cudaGetSymbolAddress((void**)&WkL, g_WkL);
    cudaGetSymbolAddress((void**)&WvH, g_WvH); cudaGetSymbolAddress((void**)&WvL, g_WvL);
    cudaGetSymbolAddress((void**)&QH,  g_QH);  cudaGetSymbolAddress((void**)&QL,  g_QL);
    cudaGetSymbolAddress((void**)&KH,  g_KH);  cudaGetSymbolAddress((void**)&KL,  g_KL);
    cudaGetSymbolAddress((void**)&VtH, g_VtH); cudaGetSymbolAddress((void**)&VtL, g_VtL);
    cudaGetSymbolAddress((void**)&PH,  g_PH);  cudaGetSymbolAddress((void**)&PL,  g_PL);
    cudaGetSymbolAddress((void**)&S,   g_S);

    cudaFuncSetAttribute(mma_nt<0>, cudaFuncAttributeMaxDynamicSharedMemorySize, SMEM_BYTES);
    cudaFuncSetAttribute(mma_nt<1>, cudaFuncAttributeMaxDynamicSharedMemorySize, SMEM_BYTES);
    cudaFuncSetAttribute(mma_nt<2>, cudaFuncAttributeMaxDynamicSharedMemorySize, SMEM_BYTES);

    const dim3 blk(512);
    const dim3 sblk(256);

    // input conversions: 2 launches total
    split_two<<<16384, sblk>>>(target, tH, tL, non_target, nH, nL);
    split_w3 <<<1536,  sblk>>>(Wq, WqH, WqL, Wk, WkH, WkL, Wv, WvH, WvL);

    // Q/K/V projections (M = B*S folded = 16384 -> 64 y-tiles, N = D, K = D)
    mma_nt<1><<<dim3(8, 64, 1), blk, SMEM_BYTES>>>(
        tH, tL, WqH, WqL, QH, QL, bq, D_, D_, 0, 0, 0, 0);
    mma_nt<1><<<dim3(8, 64, 1), blk, SMEM_BYTES>>>(
        nH, nL, WkH, WkL, KH, KL, bk, D_, D_, 0, 0, 0, 0);
    mma_nt<2><<<dim3(8, 64, 1), blk, SMEM_BYTES>>>(
        nH, nL, WvH, WvL, VtH, VtL, bv, D_, D_, 0, 0, 0, SKV_);

    // S[b] = Q[b] @ K[b]^T   (M=2048 -> 8 y-tiles, N=2048 -> 16 x-tiles)
    mma_nt<0><<<dim3(16, 8, 8), blk, SMEM_BYTES>>>(
        QH, QL, KH, KL, S, nullptr, nullptr, D_, SKV_,
        (long long)SQ_ * D_, (long long)SKV_ * D_, (long long)SQ_ * SKV_, 0);

    // softmax + split conversion of P
    softmax_split<<<B_ * SQ_, sblk>>>(S, PH, PL);

    // O[b] = P[b] @ Vt[b]^T  (M=2048 -> 8 y-tiles, N=1024 -> 8 x-tiles)
    mma_nt<0><<<dim3(8, 8, 8), blk, SMEM_BYTES>>>(
        PH, PL, VtH, VtL, out, nullptr, nullptr, SKV_, D_,
        (long long)SQ_ * SKV_, (long long)D_ * SKV_, (long long)SQ_ * D_, 0);
}

// round 14
// speedup vs baseline: 1.0916x; 1.0916x over previous
#include <cuda_runtime.h>
#include <cuda_bf16.h>
#include <math.h>
#include <stdint.h>

#define B_   8
#define SQ_  2048
#define SKV_ 2048
#define D_   1024

typedef __nv_bfloat16 bf16;

// ---------------------------------------------------------------------------
// Device scratch (allocation-free per harness rules)
// ---------------------------------------------------------------------------
__device__ bf16 g_tH [16777216], g_tL [16777216];   // target split
__device__ bf16 g_nH [16777216], g_nL [16777216];   // non_target split
__device__ bf16 g_WqH[ 1048576], g_WqL[ 1048576];
__device__ bf16 g_WkH[ 1048576], g_WkL[ 1048576];
__device__ bf16 g_WvH[ 1048576], g_WvL[ 1048576];
__device__ bf16 g_QH [16777216], g_QL [16777216];
__device__ bf16 g_KH [16777216], g_KL [16777216];
__device__ bf16 g_VtH[16777216], g_VtL[16777216];   // V^T per batch [b][d][kv]
__device__ float g_S [33554432];                    // scores fp32
__device__ bf16 g_PH [33554432], g_PL [33554432];   // probs split

__device__ __forceinline__ uint32_t smem_u32(const void* p) {
    uint32_t a;
    asm("{ .reg .u64 t; cvta.to.shared.u64 t, %1; cvt.u32.u64 %0, t; }" : "=r"(a) : "l"(p));
    return a;
}

// ---------------------------------------------------------------------------
// Warp-MMA primitives (sm_80 baseline; safe under compute_103)
// ---------------------------------------------------------------------------
#define LDSM4(r, ad) \
    asm volatile("ldmatrix.sync.aligned.m8n8.x4.shared.b16 {%0,%1,%2,%3}, [%4];" \
        : "=r"((r)[0]), "=r"((r)[1]), "=r"((r)[2]), "=r"((r)[3]) : "r"(ad))

#define MMA_BF16(c, a, b) \
    asm volatile("mma.sync.aligned.m16n8k16.row.col.f32.bf16.bf16.f32 " \
        "{%0,%1,%2,%3}, {%4,%5,%6,%7}, {%8,%9}, {%0,%1,%2,%3};" \
        : "+f"((c)[0]), "+f"((c)[1]), "+f"((c)[2]), "+f"((c)[3]) \
        : "r"((a)[0]), "r"((a)[1]), "r"((a)[2]), "r"((a)[3]), \
          "r"((b)[0]), "r"((b)[1]))

#define CP_ASYNC16(dst, src) \
    asm volatile("cp.async.cg.shared.global [%0], [%1], 16;" :: "r"(dst), "l"(src))
#define CP_COMMIT()  asm volatile("cp.async.commit_group;" ::: "memory")
#define CP_WAIT1()   asm volatile("cp.async.wait_group 1;" ::: "memory")

// ---------------------------------------------------------------------------
// Split-bf16 NT GEMM: C = (Ah+Al)(Bh+Bl)^T ~= hh+hl+lh (+bias)
// CTA tile 128x128, BK=32, 8 warps (2m x 4n, warp tile 64x32), 256 threads.
// 2-stage cp.async pipeline, single fragment buffer, <=128 regs so that
// TWO independent CTAs are resident per SM: their uncorrelated barrier
// phases keep the tensor pipe fed during each other's load windows.
// EPI: 0 = fp32 C, 1 = split-bf16 + bias, 2 = split-bf16 transposed + bias
// ---------------------------------------------------------------------------
#define STAGES 2
#define ROWB  80                       // 32 bf16 (64B) + 16B pad (conflict-free)
#define PLANE (128 * ROWB)             // 10240 B
#define STAGE_BYTES (4 * PLANE)        // 40960 B
#define SMEM_BYTES (STAGES * STAGE_BYTES)  // 81920 B -> 2 CTAs/SM

template <int EPI>
__global__ void __launch_bounds__(256, 2)
mma_nt(const bf16* __restrict__ Ah, const bf16* __restrict__ Al,
       const bf16* __restrict__ Bh, const bf16* __restrict__ Bl,
       void* __restrict__ C0, void* __restrict__ C1,
       const float* __restrict__ bias,
       int K, int ldC,
       long long sA, long long sB, long long sC, int batchRows)
{
    extern __shared__ __align__(128) char smem[];
    const uint32_t sbase = smem_u32(smem);
    const int tid  = threadIdx.x;
    const int lane = tid & 31;
    const int wid  = tid >> 5;
    const int wm   = wid & 1;      // 2 warps along m (64 rows each)
    const int wn   = wid >> 1;     // 4 warps along n (32 cols each)

    Ah += (long long)blockIdx.z * sA;  Al += (long long)blockIdx.z * sA;
    Bh += (long long)blockIdx.z * sB;  Bl += (long long)blockIdx.z * sB;

    const int m0 = blockIdx.y * 128;
    const int n0 = blockIdx.x * 128;
    const int nChunks = K >> 5;

    // --- cp.async one K-chunk (4 planes x 128 rows x 64B) into a stage -----
    // 2048 16B-chunks over 256 threads = 8 per thread.
    auto issue = [&](int t) {
        if (t < nChunks) {
            const int stage = t & 1;
            const int k0 = t << 5;
#pragma unroll
            for (int i = 0; i < 8; ++i) {
                const int idx = tid + (i << 8);       // 0..2047
                const int c = idx & 3;                // 16B chunk within row
                const int r = (idx >> 2) & 127;       // tile row
                const int p = idx >> 9;               // plane
                const bf16* src;
                if      (p == 0) src = Ah + (size_t)(m0 + r) * K + k0 + c * 8;
                else if (p == 1) src = Al + (size_t)(m0 + r) * K + k0 + c * 8;
                else if (p == 2) src = Bh + (size_t)(n0 + r) * K + k0 + c * 8;
                else             src = Bl + (size_t)(n0 + r) * K + k0 + c * 8;
                const uint32_t dst = sbase + stage * STAGE_BYTES + p * PLANE
                                   + r * ROWB + c * 16;
                CP_ASYNC16(dst, src);
            }
        }
        CP_COMMIT();
    };

    float acc[4][4][4];
#pragma unroll
    for (int mi = 0; mi < 4; ++mi)
#pragma unroll
        for (int ni = 0; ni < 4; ++ni)
#pragma unroll
            for (int e = 0; e < 4; ++e) acc[mi][ni][e] = 0.0f;

    const uint32_t arow = (uint32_t)(wm * 64 + (lane & 15));
    const uint32_t abit = (uint32_t)((lane >> 4) << 4);
    const uint32_t brow = (uint32_t)(wn * 32 + (lane & 7) + ((lane >> 4) << 3));
    const uint32_t bbit = (uint32_t)(((lane >> 3) & 1) << 4);

    issue(0);

    for (int t = 0; t < nChunks; ++t) {
        __syncthreads();     // all warps done reading stage (t+1)&1 (iter t-1)
        issue(t + 1);        // overwrite it with chunk t+1
        CP_WAIT1();          // chunk t resident (this thread); t+1 in flight
        __syncthreads();     // chunk t visible to all warps

        const uint32_t st = sbase + (t & 1) * STAGE_BYTES;
#pragma unroll
        for (int ks = 0; ks < 2; ++ks) {
            uint32_t ah[4][4], al[4][4], bh[2][4], bl[2][4];
            const uint32_t akoff = (uint32_t)(ks << 5) + abit;
#pragma unroll
            for (int mi = 0; mi < 4; ++mi) {
                const uint32_t ad = st + (arow + mi * 16) * ROWB + akoff;
                LDSM4(ah[mi], ad);
                LDSM4(al[mi], ad + PLANE);
            }
            const uint32_t bkoff = (uint32_t)(ks << 5) + bbit;
#pragma unroll
            for (int np = 0; np < 2; ++np) {
                const uint32_t bd = st + 2 * PLANE + (brow + np * 16) * ROWB + bkoff;
                LDSM4(bh[np], bd);
                LDSM4(bl[np], bd + PLANE);
            }
#pragma unroll
            for (int mi = 0; mi < 4; ++mi)
#pragma unroll
                for (int ni = 0; ni < 4; ++ni) {
                    const uint32_t* bhp = &bh[ni >> 1][(ni & 1) << 1];
                    const uint32_t* blp = &bl[ni >> 1][(ni & 1) << 1];
                    MMA_BF16(acc[mi][ni], ah[mi], bhp);
                    MMA_BF16(acc[mi][ni], ah[mi], blp);
                    MMA_BF16(acc[mi][ni], al[mi], bhp);
                }
        }
    }

    // ---------------------------- epilogue ---------------------------------
    const int qr = lane >> 2;          // 0..7
    const int qc = (lane & 3) << 1;    // 0,2,4,6

#pragma unroll
    for (int mi = 0; mi < 4; ++mi) {
        const int gm0 = m0 + wm * 64 + mi * 16 + qr;   // row, and gm0+8
#pragma unroll
        for (int ni = 0; ni < 4; ++ni) {
            const int gn = n0 + wn * 32 + ni * 8 + qc;
            float v00 = acc[mi][ni][0], v01 = acc[mi][ni][1];
            float v10 = acc[mi][ni][2], v11 = acc[mi][ni][3];

            if (EPI == 0) {
                float* C = (float*)C0 + (long long)blockIdx.z * sC;
                *reinterpret_cast<float2*>(C + (size_t)gm0 * ldC + gn)
                    = make_float2(v00, v01);
                *reinterpret_cast<float2*>(C + (size_t)(gm0 + 8) * ldC + gn)
                    = make_float2(v10, v11);
            } else {
                const float b0v = bias[gn], b1v = bias[gn + 1];
                v00 += b0v; v01 += b1v; v10 += b0v; v11 += b1v;
                bf16 h00 = __float2bfloat16(v00);
                bf16 h01 = __float2bfloat16(v01);
                bf16 h10 = __float2bfloat16(v10);
                bf16 h11 = __float2bfloat16(v11);
                bf16 l00 = __float2bfloat16(v00 - __bfloat162float(h00));
                bf16 l01 = __float2bfloat16(v01 - __bfloat162float(h01));
                bf16 l10 = __float2bfloat16(v10 - __bfloat162float(h10));
                bf16 l11 = __float2bfloat16(v11 - __bfloat162float(h11));
                bf16* CH = (bf16*)C0;
                bf16* CL = (bf16*)C1;
                if (EPI == 1) {
                    __nv_bfloat162 hp0; hp0.x = h00; hp0.y = h01;
                    __nv_bfloat162 hp1; hp1.x = h10; hp1.y = h11;
                    __nv_bfloat162 lp0; lp0.x = l00; lp0.y = l01;
                    __nv_bfloat162 lp1; lp1.x = l10; lp1.y = l11;
                    *reinterpret_cast<__nv_bfloat162*>(CH + (size_t)gm0 * ldC + gn) = hp0;
                    *reinterpret_cast<__nv_bfloat162*>(CH + (size_t)(gm0 + 8) * ldC + gn) = hp1;
                    *reinterpret_cast<__nv_bfloat162*>(CL + (size_t)gm0 * ldC + gn) = lp0;
                    *reinterpret_cast<__nv_bfloat162*>(CL + (size_t)(gm0 + 8) * ldC + gn) = lp1;
                } else {  // EPI == 2: V^T scatter (gm -> (bb, s), col-major per batch)
                    const int bb = gm0 / batchRows;
                    const int s0 = gm0 - bb * batchRows;
                    const size_t colbase = ((size_t)bb * ldC + gn) * (size_t)batchRows;
                    CH[colbase + s0]                  = h00;
                    CH[colbase + batchRows + s0]      = h01;
                    CH[colbase + s0 + 8]              = h10;
                    CH[colbase + batchRows + s0 + 8]  = h11;
                    CL[colbase + s0]                  = l00;
                    CL[colbase + batchRows + s0]      = l01;
                    CL[colbase + s0 + 8]              = l10;
                    CL[colbase + batchRows + s0 + 8]  = l11;
                }
            }
        }
    }
}

// ---------------------------------------------------------------------------
// Split helpers: fp32 -> (bf16 hi, bf16 lo), 8 elems/thread, fully coalesced.
// ---------------------------------------------------------------------------
__device__ __forceinline__ void split8(const float* __restrict__ x,
                                       bf16* __restrict__ h, bf16* __restrict__ l,
                                       int i)
{
    const float4 a = reinterpret_cast<const float4*>(x)[2 * i];
    const float4 b = reinterpret_cast<const float4*>(x)[2 * i + 1];
    float v[8] = { a.x, a.y, a.z, a.w, b.x, b.y, b.z, b.w };
    __align__(16) bf16 hb[8];
    __align__(16) bf16 lb[8];
#pragma unroll
    for (int j = 0; j < 8; ++j) {
        bf16 hh = __float2bfloat16(v[j]);
        hb[j] = hh;
        lb[j] = __float2bfloat16(v[j] - __bfloat162float(hh));
    }
    reinterpret_cast<uint4*>(h)[i] = *reinterpret_cast<uint4*>(hb);
    reinterpret_cast<uint4*>(l)[i] = *reinterpret_cast<uint4*>(lb);
}

// target + non_target in ONE launch
__global__ void split_two(const float* __restrict__ x0, bf16* __restrict__ h0, bf16* __restrict__ l0,
                          const float* __restrict__ x1, bf16* __restrict__ h1, bf16* __restrict__ l1)
{
    int b = blockIdx.x;
    const float* x; bf16 *h, *l;
    if (b < 8192) { x = x0; h = h0; l = l0; }
    else          { x = x1; h = h1; l = l1; b -= 8192; }
    split8(x, h, l, b * 256 + (int)threadIdx.x);
}

// three weight matrices in ONE launch: 512 blocks each
__global__ void split_w3(const float* __restrict__ wq, bf16* __restrict__ qh, bf16* __restrict__ ql,
                         const float* __restrict__ wk, bf16* __restrict__ kh, bf16* __restrict__ kl,
                         const float* __restrict__ wv, bf16* __restrict__ vh, bf16* __restrict__ vl)
{
    int b = blockIdx.x;
    const float* x; bf16 *h, *l;
    if (b < 512)       { x = wq; h = qh; l = ql; }
    else if (b < 1024) { x = wk; h = kh; l = kl; b -= 512; }
    else               { x = wv; h = vh; l = vl; b -= 1024; }
    split8(x, h, l, b * 256 + (int)threadIdx.x);
}

// ---------------------------------------------------------------------------
// Row softmax (2048 cols) fused with split-bf16 conversion; vectorized
// ---------------------------------------------------------------------------
__global__ __launch_bounds__(256)
void softmax_split(const float* __restrict__ S, bf16* __restrict__ Ph, bf16* __restrict__ Pl)
{
    const size_t base = (size_t)blockIdx.x * SKV_;
    const float* p = S + base;
    const int tid = threadIdx.x;
    const int lane = tid & 31;
    const int warp = tid >> 5;
    __shared__ float red[8];

    const float4 a = reinterpret_cast<const float4*>(p)[2 * tid];
    const float4 b = reinterpret_cast<const float4*>(p)[2 * tid + 1];
    float v[8] = { a.x, a.y, a.z, a.w, b.x, b.y, b.z, b.w };

    float m = -INFINITY;
#pragma unroll
    for (int i = 0; i < 8; ++i) m = fmaxf(m, v[i]);
#pragma unroll
    for (int o = 16; o > 0; o >>= 1) m = fmaxf(m, __shfl_xor_sync(0xffffffffu, m, o));
    if (lane == 0) red[warp] = m;
    __syncthreads();
    float mrow = red[0];
#pragma unroll
    for (int w = 1; w < 8; ++w) mrow = fmaxf(mrow, red[w]);
    __syncthreads();

    float s = 0.0f;
#pragma unroll
    for (int i = 0; i < 8; ++i) { v[i] = expf(v[i] - mrow); s += v[i]; }
#pragma unroll
    for (int o = 16; o > 0; o >>= 1) s += __shfl_xor_sync(0xffffffffu, s, o);
    if (lane == 0) red[warp] = s;
    __syncthreads();
    float srow = 0.0f;
#pragma unroll
    for (int w = 0; w < 8; ++w) srow += red[w];
    const float inv = 1.0f / srow;

    __align__(16) bf16 hb[8];
    __align__(16) bf16 lb[8];
#pragma unroll
    for (int i = 0; i < 8; ++i) {
        float pv = v[i] * inv;
        bf16 h = __float2bfloat16(pv);
        hb[i] = h;
        lb[i] = __float2bfloat16(pv - __bfloat162float(h));
    }
    reinterpret_cast<uint4*>(Ph + base)[tid] = *reinterpret_cast<uint4*>(hb);
    reinterpret_cast<uint4*>(Pl + base)[tid] = *reinterpret_cast<uint4*>(lb);
}

// ---------------------------------------------------------------------------
// Launch
// ---------------------------------------------------------------------------
extern "C" void kernel_launch(void* const* d_in, const int* in_sizes, int n_in,
                              void* d_out, int out_size)
{
    const float* target     = (const float*)d_in[0];
    const float* non_target = (const float*)d_in[1];
    const float* Wq = (const float*)d_in[2];
    const float* bq = (const float*)d_in[3];
    const float* Wk = (const float*)d_in[4];
    const float* bk = (const float*)d_in[5];
    const float* Wv = (const float*)d_in[6];
    const float* bv = (const float*)d_in[7];
    float* out = (float*)d_out;

    bf16 *tH, *tL, *nH, *nL, *WqH, *WqL, *WkH, *WkL, *WvH, *WvL;
    bf16 *QH, *QL, *KH, *KL, *VtH, *VtL, *PH, *PL;
    float* S;
    cudaGetSymbolAddress((void**)&tH,  g_tH);  cudaGetSymbolAddress((void**)&tL,  g_tL);
    cudaGetSymbolAddress((void**)&nH,  g_nH);  cudaGetSymbolAddress((void**)&nL,  g_nL);
    cudaGetSymbolAddress((void**)&WqH, g_WqH); cudaGetSymbolAddress((void**)&WqL, g_WqL);
    cudaGetSymbolAddress((void**)&WkH, g_WkH); cudaGetSymbolAddress((void**)&WkL, g_WkL);
    cudaGetSymbolAddress((void**)&WvH, g_WvH); cudaGetSymbolAddress((void**)&WvL, g_WvL);
    cudaGetSymbolAddress((void**)&QH,  g_QH);  cudaGetSymbolAddress((void**)&QL,  g_QL);
    cudaGetSymbolAddress((void**)&KH,  g_KH);  cudaGetSymbolAddress((void**)&KL,  g_KL);
    cudaGetSymbolAddress((void**)&VtH, g_VtH); cudaGetSymbolAddress((void**)&VtL, g_VtL);
    cudaGetSymbolAddress((void**)&PH,  g_PH);  cudaGetSymbolAddress((void**)&PL,  g_PL);
    cudaGetSymbolAddress((void**)&S,   g_S);

    cudaFuncSetAttribute(mma_nt<0>, cudaFuncAttributeMaxDynamicSharedMemorySize, SMEM_BYTES);
    cudaFuncSetAttribute(mma_nt<1>, cudaFuncAttributeMaxDynamicSharedMemorySize, SMEM_BYTES);
    cudaFuncSetAttribute(mma_nt<2>, cudaFuncAttributeMaxDynamicSharedMemorySize, SMEM_BYTES);

    const dim3 blk(256);

    // input conversions: 2 launches total
    split_two<<<16384, blk>>>(target, tH, tL, non_target, nH, nL);
    split_w3 <<<1536,  blk>>>(Wq, WqH, WqL, Wk, WkH, WkL, Wv, WvH, WvL);

    // Q/K/V projections (M = B*S folded, N = D, K = D)
    mma_nt<1><<<dim3(8, 128, 1), blk, SMEM_BYTES>>>(
        tH, tL, WqH, WqL, QH, QL, bq, D_, D_, 0, 0, 0, 0);
    mma_nt<1><<<dim3(8, 128, 1), blk, SMEM_BYTES>>>(
        nH, nL, WkH, WkL, KH, KL, bk, D_, D_, 0, 0, 0, 0);
    mma_nt<2><<<dim3(8, 128, 1), blk, SMEM_BYTES>>>(
        nH, nL, WvH, WvL, VtH, VtL, bv, D_, D_, 0, 0, 0, SKV_);

    // S[b] = Q[b] @ K[b]^T
    mma_nt<0><<<dim3(16, 16, 8), blk, SMEM_BYTES>>>(
        QH, QL, KH, KL, S, nullptr, nullptr, D_, SKV_,
        (long long)SQ_ * D_, (long long)SKV_ * D_, (long long)SQ_ * SKV_, 0);

    // softmax + split conversion of P
    softmax_split<<<B_ * SQ_, blk>>>(S, PH, PL);

    // O[b] = P[b] @ Vt[b]^T
    mma_nt<0><<<dim3(8, 16, 8), blk, SMEM_BYTES>>>(
        PH, PL, VtH, VtL, out, nullptr, nullptr, SKV_, D_,
        (long long)SQ_ * SKV_, (long long)D_ * SKV_, (long long)SQ_ * D_, 0);
}

// round 15
// speedup vs baseline: 1.1278x; 1.0331x over previous
#include <cuda_runtime.h>
#include <cuda_bf16.h>
#include <math.h>
#include <stdint.h>

#define B_   8
#define SQ_  2048
#define SKV_ 2048
#define D_   1024

typedef __nv_bfloat16 bf16;

// ---------------------------------------------------------------------------
// Device scratch (allocation-free per harness rules)
// ---------------------------------------------------------------------------
__device__ bf16 g_tH [16777216], g_tL [16777216];   // target split
__device__ bf16 g_nH [16777216], g_nL [16777216];   // non_target split
__device__ bf16 g_WqH[ 1048576], g_WqL[ 1048576];
__device__ bf16 g_WkH[ 1048576], g_WkL[ 1048576];
__device__ bf16 g_WvH[ 1048576], g_WvL[ 1048576];
__device__ bf16 g_QH [16777216], g_QL [16777216];
__device__ bf16 g_KH [16777216], g_KL [16777216];
__device__ bf16 g_VtH[16777216], g_VtL[16777216];   // V^T per batch [b][d][kv]
__device__ float g_S [33554432];                    // scores fp32
__device__ bf16 g_PH [33554432], g_PL [33554432];   // probs split

__device__ __forceinline__ uint32_t smem_u32(const void* p) {
    uint32_t a;
    asm("{ .reg .u64 t; cvta.to.shared.u64 t, %1; cvt.u32.u64 %0, t; }" : "=r"(a) : "l"(p));
    return a;
}

// ---------------------------------------------------------------------------
// Warp-MMA primitives (sm_80 baseline; safe under compute_103)
// ---------------------------------------------------------------------------
#define LDSM4(r, ad) \
    asm volatile("ldmatrix.sync.aligned.m8n8.x4.shared.b16 {%0,%1,%2,%3}, [%4];" \
        : "=r"((r)[0]), "=r"((r)[1]), "=r"((r)[2]), "=r"((r)[3]) : "r"(ad))

#define MMA_BF16(c, a, b) \
    asm volatile("mma.sync.aligned.m16n8k16.row.col.f32.bf16.bf16.f32 " \
        "{%0,%1,%2,%3}, {%4,%5,%6,%7}, {%8,%9}, {%0,%1,%2,%3};" \
        : "+f"((c)[0]), "+f"((c)[1]), "+f"((c)[2]), "+f"((c)[3]) \
        : "r"((a)[0]), "r"((a)[1]), "r"((a)[2]), "r"((a)[3]), \
          "r"((b)[0]), "r"((b)[1]))

#define CP_ASYNC16(dst, src) \
    asm volatile("cp.async.cg.shared.global [%0], [%1], 16;" :: "r"(dst), "l"(src))
#define CP_COMMIT()  asm volatile("cp.async.commit_group;" ::: "memory")
#define CP_WAIT1()   asm volatile("cp.async.wait_group 1;" ::: "memory")
#define CP_WAIT0()   asm volatile("cp.async.wait_group 0;" ::: "memory")

// ---------------------------------------------------------------------------
// Split-bf16 NT GEMM (R11 champion): C = (Ah+Al)(Bh+Bl)^T ~= hh+hl+lh (+bias)
// CTA tile 128x128, chunk BK=64 (4 ks-steps), 8 warps (2m x 4n),
// 3-stage cp.async pipeline, register double-buffered fragments.
// EPI: 0 = fp32 C, 1 = split-bf16 + bias,
//      2 = split-bf16 transposed + bias via SMEM-staged coalesced stores
// ---------------------------------------------------------------------------
#define STAGES 3
#define ROWB  144                      // 64 bf16 (128B) + 16B pad
#define PLANE (128 * ROWB)             // 18432 B
#define STAGE_BYTES (4 * PLANE)        // 73728 B
#define SMEM_BYTES (STAGES * STAGE_BYTES)  // 221184 B

// transpose-staging layout (EPI=2 epilogue, reuses stage memory):
// plane h: rows = d (128), row stride 272 B (256 B data + 16 B pad), plane l after.
#define TR_ROWB  272
#define TR_PLANE (128 * TR_ROWB)       // 34816 B; 2 planes = 69632 B < SMEM_BYTES

template <int EPI>
__global__ void __launch_bounds__(256, 1)
mma_nt(const bf16* __restrict__ Ah, const bf16* __restrict__ Al,
       const bf16* __restrict__ Bh, const bf16* __restrict__ Bl,
       void* __restrict__ C0, void* __restrict__ C1,
       const float* __restrict__ bias,
       int K, int ldC,
       long long sA, long long sB, long long sC, int batchRows)
{
    extern __shared__ __align__(128) char smem[];
    const uint32_t sbase = smem_u32(smem);
    const int tid  = threadIdx.x;
    const int lane = tid & 31;
    const int wid  = tid >> 5;
    const int wm   = wid & 1;      // 2 warps along m
    const int wn   = wid >> 1;     // 4 warps along n

    Ah += (long long)blockIdx.z * sA;  Al += (long long)blockIdx.z * sA;
    Bh += (long long)blockIdx.z * sB;  Bl += (long long)blockIdx.z * sB;

    const int m0 = blockIdx.y * 128;
    const int n0 = blockIdx.x * 128;
    const int nChunks = K >> 6;

    auto issue = [&](int t) {
        if (t < nChunks) {
            const int stage = t % STAGES;
            const int k0 = t << 6;
#pragma unroll
            for (int i = 0; i < 16; ++i) {
                const int idx = tid + (i << 8);       // 0..4095
                const int c = idx & 7;
                const int r = (idx >> 3) & 127;
                const int p = idx >> 10;
                const bf16* src;
                if      (p == 0) src = Ah + (size_t)(m0 + r) * K + k0 + c * 8;
                else if (p == 1) src = Al + (size_t)(m0 + r) * K + k0 + c * 8;
                else if (p == 2) src = Bh + (size_t)(n0 + r) * K + k0 + c * 8;
                else             src = Bl + (size_t)(n0 + r) * K + k0 + c * 8;
                const uint32_t dst = sbase + stage * STAGE_BYTES + p * PLANE
                                   + r * ROWB + c * 16;
                CP_ASYNC16(dst, src);
            }
        }
        CP_COMMIT();
    };

    float acc[4][4][4];
#pragma unroll
    for (int mi = 0; mi < 4; ++mi)
#pragma unroll
        for (int ni = 0; ni < 4; ++ni)
#pragma unroll
            for (int e = 0; e < 4; ++e) acc[mi][ni][e] = 0.0f;

    uint32_t ah[2][4][4], al[2][4][4], bh[2][2][4], bl[2][2][4];

    const uint32_t arow = (uint32_t)(wm * 64 + (lane & 15));
    const uint32_t abit = (uint32_t)((lane >> 4) << 4);
    const uint32_t brow = (uint32_t)(wn * 32 + (lane & 7) + ((lane >> 4) << 3));
    const uint32_t bbit = (uint32_t)(((lane >> 3) & 1) << 4);

    auto ldfrag = [&](uint32_t st, int ks, int buf) {
        const uint32_t akoff = (uint32_t)(ks << 5) + abit;
#pragma unroll
        for (int mi = 0; mi < 4; ++mi) {
            const uint32_t ad = st + (arow + mi * 16) * ROWB + akoff;
            LDSM4(ah[buf][mi], ad);
            LDSM4(al[buf][mi], ad + PLANE);
        }
        const uint32_t bkoff = (uint32_t)(ks << 5) + bbit;
#pragma unroll
        for (int np = 0; np < 2; ++np) {
            const uint32_t bd = st + 2 * PLANE + (brow + np * 16) * ROWB + bkoff;
            LDSM4(bh[buf][np], bd);
            LDSM4(bl[buf][np], bd + PLANE);
        }
    };

    issue(0);
    issue(1);

    for (int t = 0; t < nChunks; ++t) {
        CP_WAIT1();
        __syncthreads();
        issue(t + 2);

        const uint32_t st = sbase + (t % STAGES) * STAGE_BYTES;
        ldfrag(st, 0, 0);
#pragma unroll
        for (int ks = 0; ks < 4; ++ks) {
            const int cur = ks & 1;
            if (ks < 3) ldfrag(st, ks + 1, cur ^ 1);
#pragma unroll
            for (int mi = 0; mi < 4; ++mi)
#pragma unroll
                for (int ni = 0; ni < 4; ++ni) {
                    const uint32_t* bhp = &bh[cur][ni >> 1][(ni & 1) << 1];
                    const uint32_t* blp = &bl[cur][ni >> 1][(ni & 1) << 1];
                    MMA_BF16(acc[mi][ni], ah[cur][mi], bhp);
                    MMA_BF16(acc[mi][ni], ah[cur][mi], blp);
                    MMA_BF16(acc[mi][ni], al[cur][mi], bhp);
                }
        }
    }

    const int qr = lane >> 2;
    const int qc = (lane & 3) << 1;

    if (EPI == 2) {
        // -------- staged transposed epilogue: coalesced V^T stores ---------
        CP_WAIT0();
        __syncthreads();               // stage memory now reusable

        // write phase: smem[d][s] (d = output column, s = tile row)
#pragma unroll
        for (int mi = 0; mi < 4; ++mi) {
            const int sr = wm * 64 + mi * 16 + qr;     // tile row, and sr+8
#pragma unroll
            for (int ni = 0; ni < 4; ++ni) {
                const int dc = wn * 32 + ni * 8 + qc;  // tile col, and dc+1
                float v00 = acc[mi][ni][0] + bias[n0 + dc];
                float v01 = acc[mi][ni][1] + bias[n0 + dc + 1];
                float v10 = acc[mi][ni][2] + bias[n0 + dc];
                float v11 = acc[mi][ni][3] + bias[n0 + dc + 1];
                bf16 h00 = __float2bfloat16(v00);
                bf16 h01 = __float2bfloat16(v01);
                bf16 h10 = __float2bfloat16(v10);
                bf16 h11 = __float2bfloat16(v11);
                bf16 l00 = __float2bfloat16(v00 - __bfloat162float(h00));
                bf16 l01 = __float2bfloat16(v01 - __bfloat162float(h01));
                bf16 l10 = __float2bfloat16(v10 - __bfloat162float(h10));
                bf16 l11 = __float2bfloat16(v11 - __bfloat162float(h11));
                char* r0 = smem + dc * TR_ROWB;
                char* r1 = smem + (dc + 1) * TR_ROWB;
                *reinterpret_cast<bf16*>(r0 + sr * 2)            = h00;
                *reinterpret_cast<bf16*>(r1 + sr * 2)            = h01;
                *reinterpret_cast<bf16*>(r0 + (sr + 8) * 2)      = h10;
                *reinterpret_cast<bf16*>(r1 + (sr + 8) * 2)      = h11;
                *reinterpret_cast<bf16*>(r0 + TR_PLANE + sr * 2)       = l00;
                *reinterpret_cast<bf16*>(r1 + TR_PLANE + sr * 2)       = l01;
                *reinterpret_cast<bf16*>(r0 + TR_PLANE + (sr + 8) * 2) = l10;
                *reinterpret_cast<bf16*>(r1 + TR_PLANE + (sr + 8) * 2) = l11;
            }
        }
        __syncthreads();

        // read phase: coalesced 16B stores; CTA covers one batch (128 | batchRows)
        bf16* CH = (bf16*)C0;
        bf16* CL = (bf16*)C1;
        const int bb = m0 / batchRows;
        const int sb = m0 - bb * batchRows;
#pragma unroll
        for (int i = 0; i < 8; ++i) {
            const int idx = tid + (i << 8);           // 0..2047
            const int d  = idx >> 4;                  // column 0..127
            const int ch = idx & 15;                  // 16B chunk within column
            uint4 vh = *reinterpret_cast<uint4*>(smem + d * TR_ROWB + ch * 16);
            uint4 vl = *reinterpret_cast<uint4*>(smem + TR_PLANE + d * TR_ROWB + ch * 16);
            const size_t go = ((size_t)bb * ldC + n0 + d) * (size_t)batchRows
                            + sb + ch * 8;
            *reinterpret_cast<uint4*>(CH + go) = vh;
            *reinterpret_cast<uint4*>(CL + go) = vl;
        }
        return;
    }

#pragma unroll
    for (int mi = 0; mi < 4; ++mi) {
        const int gm0 = m0 + wm * 64 + mi * 16 + qr;
#pragma unroll
        for (int ni = 0; ni < 4; ++ni) {
            const int gn = n0 + wn * 32 + ni * 8 + qc;
            float v00 = acc[mi][ni][0], v01 = acc[mi][ni][1];
            float v10 = acc[mi][ni][2], v11 = acc[mi][ni][3];

            if (EPI == 0) {
                float* C = (float*)C0 + (long long)blockIdx.z * sC;
                *reinterpret_cast<float2*>(C + (size_t)gm0 * ldC + gn)
                    = make_float2(v00, v01);
                *reinterpret_cast<float2*>(C + (size_t)(gm0 + 8) * ldC + gn)
                    = make_float2(v10, v11);
            } else {  // EPI == 1
                const float b0v = bias[gn], b1v = bias[gn + 1];
                v00 += b0v; v01 += b1v; v10 += b0v; v11 += b1v;
                bf16 h00 = __float2bfloat16(v00);
                bf16 h01 = __float2bfloat16(v01);
                bf16 h10 = __float2bfloat16(v10);
                bf16 h11 = __float2bfloat16(v11);
                bf16 l00 = __float2bfloat16(v00 - __bfloat162float(h00));
                bf16 l01 = __float2bfloat16(v01 - __bfloat162float(h01));
                bf16 l10 = __float2bfloat16(v10 - __bfloat162float(h10));
                bf16 l11 = __float2bfloat16(v11 - __bfloat162float(h11));
                bf16* CH = (bf16*)C0;
                bf16* CL = (bf16*)C1;
                __nv_bfloat162 hp0; hp0.x = h00; hp0.y = h01;
                __nv_bfloat162 hp1; hp1.x = h10; hp1.y = h11;
                __nv_bfloat162 lp0; lp0.x = l00; lp0.y = l01;
                __nv_bfloat162 lp1; lp1.x = l10; lp1.y = l11;
                *reinterpret_cast<__nv_bfloat162*>(CH + (size_t)gm0 * ldC + gn) = hp0;
                *reinterpret_cast<__nv_bfloat162*>(CH + (size_t)(gm0 + 8) * ldC + gn) = hp1;
                *reinterpret_cast<__nv_bfloat162*>(CL + (size_t)gm0 * ldC + gn) = lp0;
                *reinterpret_cast<__nv_bfloat162*>(CL + (size_t)(gm0 + 8) * ldC + gn) = lp1;
            }
        }
    }
}

// ---------------------------------------------------------------------------
// Split helpers: fp32 -> (bf16 hi, bf16 lo), 8 elems/thread, fully coalesced.
// ---------------------------------------------------------------------------
__device__ __forceinline__ void split8(const float* __restrict__ x,
                                       bf16* __restrict__ h, bf16* __restrict__ l,
                                       int i)
{
    const float4 a = reinterpret_cast<const float4*>(x)[2 * i];
    const float4 b = reinterpret_cast<const float4*>(x)[2 * i + 1];
    float v[8] = { a.x, a.y, a.z, a.w, b.x, b.y, b.z, b.w };
    __align__(16) bf16 hb[8];
    __align__(16) bf16 lb[8];
#pragma unroll
    for (int j = 0; j < 8; ++j) {
        bf16 hh = __float2bfloat16(v[j]);
        hb[j] = hh;
        lb[j] = __float2bfloat16(v[j] - __bfloat162float(hh));
    }
    reinterpret_cast<uint4*>(h)[i] = *reinterpret_cast<uint4*>(hb);
    reinterpret_cast<uint4*>(l)[i] = *reinterpret_cast<uint4*>(lb);
}

// target + non_target in ONE launch
__global__ void split_two(const float* __restrict__ x0, bf16* __restrict__ h0, bf16* __restrict__ l0,
                          const float* __restrict__ x1, bf16* __restrict__ h1, bf16* __restrict__ l1)
{
    int b = blockIdx.x;
    const float* x; bf16 *h, *l;
    if (b < 8192) { x = x0; h = h0; l = l0; }
    else          { x = x1; h = h1; l = l1; b -= 8192; }
    split8(x, h, l, b * 256 + (int)threadIdx.x);
}

// three weight matrices in ONE launch: 512 blocks each
__global__ void split_w3(const float* __restrict__ wq, bf16* __restrict__ qh, bf16* __restrict__ ql,
                         const float* __restrict__ wk, bf16* __restrict__ kh, bf16* __restrict__ kl,
                         const float* __restrict__ wv, bf16* __restrict__ vh, bf16* __restrict__ vl)
{
    int b = blockIdx.x;
    const float* x; bf16 *h, *l;
    if (b < 512)       { x = wq; h = qh; l = ql; }
    else if (b < 1024) { x = wk; h = kh; l = kl; b -= 512; }
    else               { x = wv; h = vh; l = vl; b -= 1024; }
    split8(x, h, l, b * 256 + (int)threadIdx.x);
}

// ---------------------------------------------------------------------------
// Row softmax (2048 cols) fused with split-bf16 conversion; vectorized
// ---------------------------------------------------------------------------
__global__ __launch_bounds__(256)
void softmax_split(const float* __restrict__ S, bf16* __restrict__ Ph, bf16* __restrict__ Pl)
{
    const size_t base = (size_t)blockIdx.x * SKV_;
    const float* p = S + base;
    const int tid = threadIdx.x;
    const int lane = tid & 31;
    const int warp = tid >> 5;
    __shared__ float red[8];

    const float4 a = reinterpret_cast<const float4*>(p)[2 * tid];
    const float4 b = reinterpret_cast<const float4*>(p)[2 * tid + 1];
    float v[8] = { a.x, a.y, a.z, a.w, b.x, b.y, b.z, b.w };

    float m = -INFINITY;
#pragma unroll
    for (int i = 0; i < 8; ++i) m = fmaxf(m, v[i]);
#pragma unroll
    for (int o = 16; o > 0; o >>= 1) m = fmaxf(m, __shfl_xor_sync(0xffffffffu, m, o));
    if (lane == 0) red[warp] = m;
    __syncthreads();
    float mrow = red[0];
#pragma unroll
    for (int w = 1; w < 8; ++w) mrow = fmaxf(mrow, red[w]);
    __syncthreads();

    float s = 0.0f;
#pragma unroll
    for (int i = 0; i < 8; ++i) { v[i] = expf(v[i] - mrow); s += v[i]; }
#pragma unroll
    for (int o = 16; o > 0; o >>= 1) s += __shfl_xor_sync(0xffffffffu, s, o);
    if (lane == 0) red[warp] = s;
    __syncthreads();
    float srow = 0.0f;
#pragma unroll
    for (int w = 0; w < 8; ++w) srow += red[w];
    const float inv = 1.0f / srow;

    __align__(16) bf16 hb[8];
    __align__(16) bf16 lb[8];
#pragma unroll
    for (int i = 0; i < 8; ++i) {
        float pv = v[i] * inv;
        bf16 h = __float2bfloat16(pv);
        hb[i] = h;
        lb[i] = __float2bfloat16(pv - __bfloat162float(h));
    }
    reinterpret_cast<uint4*>(Ph + base)[tid] = *reinterpret_cast<uint4*>(hb);
    reinterpret_cast<uint4*>(Pl + base)[tid] = *reinterpret_cast<uint4*>(lb);
}

// ---------------------------------------------------------------------------
// Launch
// ---------------------------------------------------------------------------
extern "C" void kernel_launch(void* const* d_in, const int* in_sizes, int n_in,
                              void* d_out, int out_size)
{
    const float* target     = (const float*)d_in[0];
    const float* non_target = (const float*)d_in[1];
    const float* Wq = (const float*)d_in[2];
    const float* bq = (const float*)d_in[3];
    const float* Wk = (const float*)d_in[4];
    const float* bk = (const float*)d_in[5];
    const float* Wv = (const float*)d_in[6];
    const float* bv = (const float*)d_in[7];
    float* out = (float*)d_out;

    bf16 *tH, *tL, *nH, *nL, *WqH, *WqL, *WkH, *WkL, *WvH, *WvL;
    bf16 *QH, *QL, *KH, *KL, *VtH, *VtL, *PH, *PL;
    float* S;
    cudaGetSymbolAddress((void**)&tH,  g_tH);  cudaGetSymbolAddress((void**)&tL,  g_tL);
    cudaGetSymbolAddress((void**)&nH,  g_nH);  cudaGetSymbolAddress((void**)&nL,  g_nL);
    cudaGetSymbolAddress((void**)&WqH, g_WqH); cudaGetSymbolAddress((void**)&WqL, g_WqL);
    cudaGetSymbolAddress((void**)&WkH, g_WkH); cudaGetSymbolAddress((void**)&WkL, g_WkL);
    cudaGetSymbolAddress((void**)&WvH, g_WvH); cudaGetSymbolAddress((void**)&WvL, g_WvL);
    cudaGetSymbolAddress((void**)&QH,  g_QH);  cudaGetSymbolAddress((void**)&QL,  g_QL);
    cudaGetSymbolAddress((void**)&KH,  g_KH);  cudaGetSymbolAddress((void**)&KL,  g_KL);
    cudaGetSymbolAddress((void**)&VtH, g_VtH); cudaGetSymbolAddress((void**)&VtL, g_VtL);
    cudaGetSymbolAddress((void**)&PH,  g_PH);  cudaGetSymbolAddress((void**)&PL,  g_PL);
    cudaGetSymbolAddress((void**)&S,   g_S);

    cudaFuncSetAttribute(mma_nt<0>, cudaFuncAttributeMaxDynamicSharedMemorySize, SMEM_BYTES);
    cudaFuncSetAttribute(mma_nt<1>, cudaFuncAttributeMaxDynamicSharedMemorySize, SMEM_BYTES);
    cudaFuncSetAttribute(mma_nt<2>, cudaFuncAttributeMaxDynamicSharedMemorySize, SMEM_BYTES);

    const dim3 blk(256);

    // input conversions: 2 launches total
    split_two<<<16384, blk>>>(target, tH, tL, non_target, nH, nL);
    split_w3 <<<1536,  blk>>>(Wq, WqH, WqL, Wk, WkH, WkL, Wv, WvH, WvL);

    // Q/K/V projections (M = B*S folded, N = D, K = D)
    mma_nt<1><<<dim3(8, 128, 1), blk, SMEM_BYTES>>>(
        tH, tL, WqH, WqL, QH, QL, bq, D_, D_, 0, 0, 0, 0);
    mma_nt<1><<<dim3(8, 128, 1), blk, SMEM_BYTES>>>(
        nH, nL, WkH, WkL, KH, KL, bk, D_, D_, 0, 0, 0, 0);
    mma_nt<2><<<dim3(8, 128, 1), blk, SMEM_BYTES>>>(
        nH, nL, WvH, WvL, VtH, VtL, bv, D_, D_, 0, 0, 0, SKV_);

    // S[b] = Q[b] @ K[b]^T
    mma_nt<0><<<dim3(16, 16, 8), blk, SMEM_BYTES>>>(
        QH, QL, KH, KL, S, nullptr, nullptr, D_, SKV_,
        (long long)SQ_ * D_, (long long)SKV_ * D_, (long long)SQ_ * SKV_, 0);

    // softmax + split conversion of P
    softmax_split<<<B_ * SQ_, blk>>>(S, PH, PL);

    // O[b] = P[b] @ Vt[b]^T
    mma_nt<0><<<dim3(8, 16, 8), blk, SMEM_BYTES>>>(
        PH, PL, VtH, VtL, out, nullptr, nullptr, SKV_, D_,
        (long long)SQ_ * SKV_, (long long)D_ * SKV_, (long long)SQ_ * D_, 0);
}

// round 16
// speedup vs baseline: 1.1415x; 1.0122x over previous
#include <cuda_runtime.h>
#include <cuda_bf16.h>
#include <math.h>
#include <stdint.h>

#define B_   8
#define SQ_  2048
#define SKV_ 2048
#define D_   1024

typedef __nv_bfloat16 bf16;

// ---------------------------------------------------------------------------
// Device scratch (allocation-free per harness rules)
// ---------------------------------------------------------------------------
__device__ bf16 g_tH [16777216], g_tL [16777216];   // target split
__device__ bf16 g_nH [16777216], g_nL [16777216];   // non_target split
__device__ bf16 g_WqH[ 1048576], g_WqL[ 1048576];
__device__ bf16 g_WkH[ 1048576], g_WkL[ 1048576];
__device__ bf16 g_WvH[ 1048576], g_WvL[ 1048576];
__device__ bf16 g_QH [16777216], g_QL [16777216];
__device__ bf16 g_KH [16777216], g_KL [16777216];
__device__ bf16 g_VtH[16777216], g_VtL[16777216];   // V^T per batch [b][d][kv]
__device__ float g_S [33554432];                    // scores fp32
__device__ bf16 g_PH [33554432], g_PL [33554432];   // probs split

__device__ __forceinline__ uint32_t smem_u32(const void* p) {
    uint32_t a;
    asm("{ .reg .u64 t; cvta.to.shared.u64 t, %1; cvt.u32.u64 %0, t; }" : "=r"(a) : "l"(p));
    return a;
}

// ---------------------------------------------------------------------------
// Warp-MMA primitives (sm_80 baseline; safe under compute_103)
// ---------------------------------------------------------------------------
#define LDSM4(r, ad) \
    asm volatile("ldmatrix.sync.aligned.m8n8.x4.shared.b16 {%0,%1,%2,%3}, [%4];" \
        : "=r"((r)[0]), "=r"((r)[1]), "=r"((r)[2]), "=r"((r)[3]) : "r"(ad))

#define MMA_BF16(c, a, b) \
    asm volatile("mma.sync.aligned.m16n8k16.row.col.f32.bf16.bf16.f32 " \
        "{%0,%1,%2,%3}, {%4,%5,%6,%7}, {%8,%9}, {%0,%1,%2,%3};" \
        : "+f"((c)[0]), "+f"((c)[1]), "+f"((c)[2]), "+f"((c)[3]) \
        : "r"((a)[0]), "r"((a)[1]), "r"((a)[2]), "r"((a)[3]), \
          "r"((b)[0]), "r"((b)[1]))

#define CP_ASYNC16(dst, src) \
    asm volatile("cp.async.cg.shared.global [%0], [%1], 16;" :: "r"(dst), "l"(src))
#define CP_COMMIT()  asm volatile("cp.async.commit_group;" ::: "memory")
#define CP_WAIT1()   asm volatile("cp.async.wait_group 1;" ::: "memory")
#define CP_WAIT0()   asm volatile("cp.async.wait_group 0;" ::: "memory")

// ---------------------------------------------------------------------------
// Split-bf16 NT GEMM core (R15 champion mainloop):
//   C = (Ah+Al)(Bh+Bl)^T ~= hh+hl+lh (+bias)
// CTA tile 128x128, chunk BK=64 (4 ks-steps), 8 warps (2m x 4n),
// 3-stage cp.async pipeline, register double-buffered fragments.
// epi: 0 = fp32 C, 1 = split-bf16 + bias,
//      2 = split-bf16 transposed + bias via SMEM-staged coalesced stores
// ---------------------------------------------------------------------------
#define STAGES 3
#define ROWB  144                      // 64 bf16 (128B) + 16B pad
#define PLANE (128 * ROWB)             // 18432 B
#define STAGE_BYTES (4 * PLANE)        // 73728 B
#define SMEM_BYTES (STAGES * STAGE_BYTES)  // 221184 B

// transpose-staging layout (epi=2 epilogue, reuses stage memory)
#define TR_ROWB  272
#define TR_PLANE (128 * TR_ROWB)       // 34816 B; 2 planes < SMEM_BYTES

__device__ __forceinline__ void gemm_core(
    char* smem, uint32_t sbase,
    const bf16* __restrict__ Ah, const bf16* __restrict__ Al,
    const bf16* __restrict__ Bh, const bf16* __restrict__ Bl,
    void* __restrict__ C0, void* __restrict__ C1,
    const float* __restrict__ bias,
    int K, int ldC, int batchRows, int m0, int n0, int epi)
{
    const int tid  = threadIdx.x;
    const int lane = tid & 31;
    const int wid  = tid >> 5;
    const int wm   = wid & 1;      // 2 warps along m
    const int wn   = wid >> 1;     // 4 warps along n

    const int nChunks = K >> 6;

    auto issue = [&](int t) {
        if (t < nChunks) {
            const int stage = t % STAGES;
            const int k0 = t << 6;
#pragma unroll
            for (int i = 0; i < 16; ++i) {
                const int idx = tid + (i << 8);       // 0..4095
                const int c = idx & 7;
                const int r = (idx >> 3) & 127;
                const int p = idx >> 10;
                const bf16* src;
                if      (p == 0) src = Ah + (size_t)(m0 + r) * K + k0 + c * 8;
                else if (p == 1) src = Al + (size_t)(m0 + r) * K + k0 + c * 8;
                else if (p == 2) src = Bh + (size_t)(n0 + r) * K + k0 + c * 8;
                else             src = Bl + (size_t)(n0 + r) * K + k0 + c * 8;
                const uint32_t dst = sbase + stage * STAGE_BYTES + p * PLANE
                                   + r * ROWB + c * 16;
                CP_ASYNC16(dst, src);
            }
        }
        CP_COMMIT();
    };

    float acc[4][4][4];
#pragma unroll
    for (int mi = 0; mi < 4; ++mi)
#pragma unroll
        for (int ni = 0; ni < 4; ++ni)
#pragma unroll
            for (int e = 0; e < 4; ++e) acc[mi][ni][e] = 0.0f;

    uint32_t ah[2][4][4], al[2][4][4], bh[2][2][4], bl[2][2][4];

    const uint32_t arow = (uint32_t)(wm * 64 + (lane & 15));
    const uint32_t abit = (uint32_t)((lane >> 4) << 4);
    const uint32_t brow = (uint32_t)(wn * 32 + (lane & 7) + ((lane >> 4) << 3));
    const uint32_t bbit = (uint32_t)(((lane >> 3) & 1) << 4);

    auto ldfrag = [&](uint32_t st, int ks, int buf) {
        const uint32_t akoff = (uint32_t)(ks << 5) + abit;
#pragma unroll
        for (int mi = 0; mi < 4; ++mi) {
            const uint32_t ad = st + (arow + mi * 16) * ROWB + akoff;
            LDSM4(ah[buf][mi], ad);
            LDSM4(al[buf][mi], ad + PLANE);
        }
        const uint32_t bkoff = (uint32_t)(ks << 5) + bbit;
#pragma unroll
        for (int np = 0; np < 2; ++np) {
            const uint32_t bd = st + 2 * PLANE + (brow + np * 16) * ROWB + bkoff;
            LDSM4(bh[buf][np], bd);
            LDSM4(bl[buf][np], bd + PLANE);
        }
    };

    issue(0);
    issue(1);

    for (int t = 0; t < nChunks; ++t) {
        CP_WAIT1();
        __syncthreads();
        issue(t + 2);

        const uint32_t st = sbase + (t % STAGES) * STAGE_BYTES;
        ldfrag(st, 0, 0);
#pragma unroll
        for (int ks = 0; ks < 4; ++ks) {
            const int cur = ks & 1;
            if (ks < 3) ldfrag(st, ks + 1, cur ^ 1);
#pragma unroll
            for (int mi = 0; mi < 4; ++mi)
#pragma unroll
                for (int ni = 0; ni < 4; ++ni) {
                    const uint32_t* bhp = &bh[cur][ni >> 1][(ni & 1) << 1];
                    const uint32_t* blp = &bl[cur][ni >> 1][(ni & 1) << 1];
                    MMA_BF16(acc[mi][ni], ah[cur][mi], bhp);
                    MMA_BF16(acc[mi][ni], ah[cur][mi], blp);
                    MMA_BF16(acc[mi][ni], al[cur][mi], bhp);
                }
        }
    }

    const int qr = lane >> 2;
    const int qc = (lane & 3) << 1;

    if (epi == 2) {
        // -------- staged transposed epilogue: coalesced V^T stores ---------
        CP_WAIT0();
        __syncthreads();               // stage memory now reusable

#pragma unroll
        for (int mi = 0; mi < 4; ++mi) {
            const int sr = wm * 64 + mi * 16 + qr;     // tile row, and sr+8
#pragma unroll
            for (int ni = 0; ni < 4; ++ni) {
                const int dc = wn * 32 + ni * 8 + qc;  // tile col, and dc+1
                float v00 = acc[mi][ni][0] + bias[n0 + dc];
                float v01 = acc[mi][ni][1] + bias[n0 + dc + 1];
                float v10 = acc[mi][ni][2] + bias[n0 + dc];
                float v11 = acc[mi][ni][3] + bias[n0 + dc + 1];
                bf16 h00 = __float2bfloat16(v00);
                bf16 h01 = __float2bfloat16(v01);
                bf16 h10 = __float2bfloat16(v10);
                bf16 h11 = __float2bfloat16(v11);
                bf16 l00 = __float2bfloat16(v00 - __bfloat162float(h00));
                bf16 l01 = __float2bfloat16(v01 - __bfloat162float(h01));
                bf16 l10 = __float2bfloat16(v10 - __bfloat162float(h10));
                bf16 l11 = __float2bfloat16(v11 - __bfloat162float(h11));
                char* r0 = smem + dc * TR_ROWB;
                char* r1 = smem + (dc + 1) * TR_ROWB;
                *reinterpret_cast<bf16*>(r0 + sr * 2)            = h00;
                *reinterpret_cast<bf16*>(r1 + sr * 2)            = h01;
                *reinterpret_cast<bf16*>(r0 + (sr + 8) * 2)      = h10;
                *reinterpret_cast<bf16*>(r1 + (sr + 8) * 2)      = h11;
                *reinterpret_cast<bf16*>(r0 + TR_PLANE + sr * 2)       = l00;
                *reinterpret_cast<bf16*>(r1 + TR_PLANE + sr * 2)       = l01;
                *reinterpret_cast<bf16*>(r0 + TR_PLANE + (sr + 8) * 2) = l10;
                *reinterpret_cast<bf16*>(r1 + TR_PLANE + (sr + 8) * 2) = l11;
            }
        }
        __syncthreads();

        bf16* CH = (bf16*)C0;
        bf16* CL = (bf16*)C1;
        const int bb = m0 / batchRows;
        const int sb = m0 - bb * batchRows;
#pragma unroll
        for (int i = 0; i < 8; ++i) {
            const int idx = tid + (i << 8);           // 0..2047
            const int d  = idx >> 4;                  // column 0..127
            const int ch = idx & 15;                  // 16B chunk within column
            uint4 vh = *reinterpret_cast<uint4*>(smem + d * TR_ROWB + ch * 16);
            uint4 vl = *reinterpret_cast<uint4*>(smem + TR_PLANE + d * TR_ROWB + ch * 16);
            const size_t go = ((size_t)bb * ldC + n0 + d) * (size_t)batchRows
                            + sb + ch * 8;
            *reinterpret_cast<uint4*>(CH + go) = vh;
            *reinterpret_cast<uint4*>(CL + go) = vl;
        }
        return;
    }

#pragma unroll
    for (int mi = 0; mi < 4; ++mi) {
        const int gm0 = m0 + wm * 64 + mi * 16 + qr;
#pragma unroll
        for (int ni = 0; ni < 4; ++ni) {
            const int gn = n0 + wn * 32 + ni * 8 + qc;
            float v00 = acc[mi][ni][0], v01 = acc[mi][ni][1];
            float v10 = acc[mi][ni][2], v11 = acc[mi][ni][3];

            if (epi == 0) {
                float* C = (float*)C0;
                *reinterpret_cast<float2*>(C + (size_t)gm0 * ldC + gn)
                    = make_float2(v00, v01);
                *reinterpret_cast<float2*>(C + (size_t)(gm0 + 8) * ldC + gn)
                    = make_float2(v10, v11);
            } else {  // epi == 1
                const float b0v = bias[gn], b1v = bias[gn + 1];
                v00 += b0v; v01 += b1v; v10 += b0v; v11 += b1v;
                bf16 h00 = __float2bfloat16(v00);
                bf16 h01 = __float2bfloat16(v01);
                bf16 h10 = __float2bfloat16(v10);
                bf16 h11 = __float2bfloat16(v11);
                bf16 l00 = __float2bfloat16(v00 - __bfloat162float(h00));
                bf16 l01 = __float2bfloat16(v01 - __bfloat162float(h01));
                bf16 l10 = __float2bfloat16(v10 - __bfloat162float(h10));
                bf16 l11 = __float2bfloat16(v11 - __bfloat162float(h11));
                bf16* CH = (bf16*)C0;
                bf16* CL = (bf16*)C1;
                __nv_bfloat162 hp0; hp0.x = h00; hp0.y = h01;
                __nv_bfloat162 hp1; hp1.x = h10; hp1.y = h11;
                __nv_bfloat162 lp0; lp0.x = l00; lp0.y = l01;
                __nv_bfloat162 lp1; lp1.x = l10; lp1.y = l11;
                *reinterpret_cast<__nv_bfloat162*>(CH + (size_t)gm0 * ldC + gn) = hp0;
                *reinterpret_cast<__nv_bfloat162*>(CH + (size_t)(gm0 + 8) * ldC + gn) = hp1;
                *reinterpret_cast<__nv_bfloat162*>(CL + (size_t)gm0 * ldC + gn) = lp0;
                *reinterpret_cast<__nv_bfloat162*>(CL + (size_t)(gm0 + 8) * ldC + gn) = lp1;
            }
        }
    }
}

// ---------------------------------------------------------------------------
// Fused Q/K/V projection: grid z picks the projection. ONE launch, 3072 CTAs.
// ---------------------------------------------------------------------------
__global__ void __launch_bounds__(256, 1)
proj3(const bf16* __restrict__ tH, const bf16* __restrict__ tL,
      const bf16* __restrict__ nH, const bf16* __restrict__ nL,
      const bf16* __restrict__ WqH, const bf16* __restrict__ WqL,
      const bf16* __restrict__ WkH, const bf16* __restrict__ WkL,
      const bf16* __restrict__ WvH, const bf16* __restrict__ WvL,
      bf16* __restrict__ QH, bf16* __restrict__ QL,
      bf16* __restrict__ KH, bf16* __restrict__ KL,
      bf16* __restrict__ VtH, bf16* __restrict__ VtL,
      const float* __restrict__ bq, const float* __restrict__ bk,
      const float* __restrict__ bv)
{
    extern __shared__ __align__(128) char smem[];
    const uint32_t sbase = smem_u32(smem);
    const int z = blockIdx.z;

    const bf16 *Ah, *Al, *Bh, *Bl;
    bf16 *C0, *C1;
    const float* bias;
    int epi;
    if (z == 0)      { Ah = tH; Al = tL; Bh = WqH; Bl = WqL; C0 = QH;  C1 = QL;  bias = bq; epi = 1; }
    else if (z == 1) { Ah = nH; Al = nL; Bh = WkH; Bl = WkL; C0 = KH;  C1 = KL;  bias = bk; epi = 1; }
    else             { Ah = nH; Al = nL; Bh = WvH; Bl = WvL; C0 = VtH; C1 = VtL; bias = bv; epi = 2; }

    gemm_core(smem, sbase, Ah, Al, Bh, Bl, C0, C1, bias,
              D_, D_, SKV_, blockIdx.y * 128, blockIdx.x * 128, epi);
}

// ---------------------------------------------------------------------------
// Batched fp32-out GEMM (scores / PV); z = batch index.
// ---------------------------------------------------------------------------
__global__ void __launch_bounds__(256, 1)
mma_nt0(const bf16* __restrict__ Ah, const bf16* __restrict__ Al,
        const bf16* __restrict__ Bh, const bf16* __restrict__ Bl,
        float* __restrict__ C,
        int K, int ldC,
        long long sA, long long sB, long long sC)
{
    extern __shared__ __align__(128) char smem[];
    const uint32_t sbase = smem_u32(smem);
    gemm_core(smem, sbase,
              Ah + (long long)blockIdx.z * sA, Al + (long long)blockIdx.z * sA,
              Bh + (long long)blockIdx.z * sB, Bl + (long long)blockIdx.z * sB,
              C + (long long)blockIdx.z * sC, nullptr, nullptr,
              K, ldC, 0, blockIdx.y * 128, blockIdx.x * 128, 0);
}

// ---------------------------------------------------------------------------
// Split: fp32 -> (bf16 hi, bf16 lo), 8 elems/thread; ALL inputs in ONE launch.
// blocks [0,8192) target | [8192,16384) non_target | then 512 each Wq/Wk/Wv
// ---------------------------------------------------------------------------
__device__ __forceinline__ void split8(const float* __restrict__ x,
                                       bf16* __restrict__ h, bf16* __restrict__ l,
                                       int i)
{
    const float4 a = reinterpret_cast<const float4*>(x)[2 * i];
    const float4 b = reinterpret_cast<const float4*>(x)[2 * i + 1];
    float v[8] = { a.x, a.y, a.z, a.w, b.x, b.y, b.z, b.w };
    __align__(16) bf16 hb[8];
    __align__(16) bf16 lb[8];
#pragma unroll
    for (int j = 0; j < 8; ++j) {
        bf16 hh = __float2bfloat16(v[j]);
        hb[j] = hh;
        lb[j] = __float2bfloat16(v[j] - __bfloat162float(hh));
    }
    reinterpret_cast<uint4*>(h)[i] = *reinterpret_cast<uint4*>(hb);
    reinterpret_cast<uint4*>(l)[i] = *reinterpret_cast<uint4*>(lb);
}

__global__ void split_all(const float* __restrict__ x0, bf16* __restrict__ h0, bf16* __restrict__ l0,
                          const float* __restrict__ x1, bf16* __restrict__ h1, bf16* __restrict__ l1,
                          const float* __restrict__ wq, bf16* __restrict__ qh, bf16* __restrict__ ql,
                          const float* __restrict__ wk, bf16* __restrict__ kh, bf16* __restrict__ kl,
                          const float* __restrict__ wv, bf16* __restrict__ vh, bf16* __restrict__ vl)
{
    int b = blockIdx.x;
    const float* x; bf16 *h, *l;
    if (b < 8192)       { x = x0; h = h0; l = l0; }
    else if (b < 16384) { x = x1; h = h1; l = l1; b -= 8192; }
    else if (b < 16896) { x = wq; h = qh; l = ql; b -= 16384; }
    else if (b < 17408) { x = wk; h = kh; l = kl; b -= 16896; }
    else                { x = wv; h = vh; l = vl; b -= 17408; }
    split8(x, h, l, b * 256 + (int)threadIdx.x);
}

// ---------------------------------------------------------------------------
// Row softmax (2048 cols) fused with split-bf16 conversion; vectorized
// ---------------------------------------------------------------------------
__global__ __launch_bounds__(256)
void softmax_split(const float* __restrict__ S, bf16* __restrict__ Ph, bf16* __restrict__ Pl)
{
    const size_t base = (size_t)blockIdx.x * SKV_;
    const float* p = S + base;
    const int tid = threadIdx.x;
    const int lane = tid & 31;
    const int warp = tid >> 5;
    __shared__ float red[8];

    const float4 a = reinterpret_cast<const float4*>(p)[2 * tid];
    const float4 b = reinterpret_cast<const float4*>(p)[2 * tid + 1];
    float v[8] = { a.x, a.y, a.z, a.w, b.x, b.y, b.z, b.w };

    float m = -INFINITY;
#pragma unroll
    for (int i = 0; i < 8; ++i) m = fmaxf(m, v[i]);
#pragma unroll
    for (int o = 16; o > 0; o >>= 1) m = fmaxf(m, __shfl_xor_sync(0xffffffffu, m, o));
    if (lane == 0) red[warp] = m;
    __syncthreads();
    float mrow = red[0];
#pragma unroll
    for (int w = 1; w < 8; ++w) mrow = fmaxf(mrow, red[w]);
    __syncthreads();

    float s = 0.0f;
#pragma unroll
    for (int i = 0; i < 8; ++i) { v[i] = expf(v[i] - mrow); s += v[i]; }
#pragma unroll
    for (int o = 16; o > 0; o >>= 1) s += __shfl_xor_sync(0xffffffffu, s, o);
    if (lane == 0) red[warp] = s;
    __syncthreads();
    float srow = 0.0f;
#pragma unroll
    for (int w = 0; w < 8; ++w) srow += red[w];
    const float inv = 1.0f / srow;

    __align__(16) bf16 hb[8];
    __align__(16) bf16 lb[8];
#pragma unroll
    for (int i = 0; i < 8; ++i) {
        float pv = v[i] * inv;
        bf16 h = __float2bfloat16(pv);
        hb[i] = h;
        lb[i] = __float2bfloat16(pv - __bfloat162float(h));
    }
    reinterpret_cast<uint4*>(Ph + base)[tid] = *reinterpret_cast<uint4*>(hb);
    reinterpret_cast<uint4*>(Pl + base)[tid] = *reinterpret_cast<uint4*>(lb);
}

// ---------------------------------------------------------------------------
// Launch
// ---------------------------------------------------------------------------
extern "C" void kernel_launch(void* const* d_in, const int* in_sizes, int n_in,
                              void* d_out, int out_size)
{
    const float* target     = (const float*)d_in[0];
    const float* non_target = (const float*)d_in[1];
    const float* Wq = (const float*)d_in[2];
    const float* bq = (const float*)d_in[3];
    const float* Wk = (const float*)d_in[4];
    const float* bk = (const float*)d_in[5];
    const float* Wv = (const float*)d_in[6];
    const float* bv = (const float*)d_in[7];
    float* out = (float*)d_out;

    bf16 *tH, *tL, *nH, *nL, *WqH, *WqL, *WkH, *WkL, *WvH, *WvL;
    bf16 *QH, *QL, *KH, *KL, *VtH, *VtL, *PH, *PL;
    float* S;
    cudaGetSymbolAddress((void**)&tH,  g_tH);  cudaGetSymbolAddress((void**)&tL,  g_tL);
    cudaGetSymbolAddress((void**)&nH,  g_nH);  cudaGetSymbolAddress((void**)&nL,  g_nL);
    cudaGetSymbolAddress((void**)&WqH, g_WqH); cudaGetSymbolAddress((void**)&WqL, g_WqL);
    cudaGetSymbolAddress((void**)&WkH, g_WkH); cudaGetSymbolAddress((void**)&WkL, g_WkL);
    cudaGetSymbolAddress((void**)&WvH, g_WvH); cudaGetSymbolAddress((void**)&WvL, g_WvL);
    cudaGetSymbolAddress((void**)&QH,  g_QH);  cudaGetSymbolAddress((void**)&QL,  g_QL);
    cudaGetSymbolAddress((void**)&KH,  g_KH);  cudaGetSymbolAddress((void**)&KL,  g_KL);
    cudaGetSymbolAddress((void**)&VtH, g_VtH); cudaGetSymbolAddress((void**)&VtL, g_VtL);
    cudaGetSymbolAddress((void**)&PH,  g_PH);  cudaGetSymbolAddress((void**)&PL,  g_PL);
    cudaGetSymbolAddress((void**)&S,   g_S);

    cudaFuncSetAttribute(proj3,   cudaFuncAttributeMaxDynamicSharedMemorySize, SMEM_BYTES);
    cudaFuncSetAttribute(mma_nt0, cudaFuncAttributeMaxDynamicSharedMemorySize, SMEM_BYTES);

    const dim3 blk(256);

    // all input conversions in ONE launch
    split_all<<<17920, blk>>>(target, tH, tL, non_target, nH, nL,
                              Wq, WqH, WqL, Wk, WkH, WkL, Wv, WvH, WvL);

    // Q/K/V projections in ONE launch (z = which projection)
    proj3<<<dim3(8, 128, 3), blk, SMEM_BYTES>>>(
        tH, tL, nH, nL, WqH, WqL, WkH, WkL, WvH, WvL,
        QH, QL, KH, KL, VtH, VtL, bq, bk, bv);

    // S[b] = Q[b] @ K[b]^T
    mma_nt0<<<dim3(16, 16, 8), blk, SMEM_BYTES>>>(
        QH, QL, KH, KL, S, D_, SKV_,
        (long long)SQ_ * D_, (long long)SKV_ * D_, (long long)SQ_ * SKV_);

    // softmax + split conversion of P
    softmax_split<<<B_ * SQ_, blk>>>(S, PH, PL);

    // O[b] = P[b] @ Vt[b]^T
    mma_nt0<<<dim3(8, 16, 8), blk, SMEM_BYTES>>>(
        PH, PL, VtH, VtL, out, SKV_, D_,
        (long long)SQ_ * SKV_, (long long)D_ * SKV_, (long long)SQ_ * D_);
}